// round 16
// baseline (speedup 1.0000x reference)
#include <cuda_runtime.h>

#define DM 24
#define RD 10
#define NSEQ 512
#define ROWS 4096
#define APAD 12
#define CQS 52
#define JCH 64

typedef unsigned long long u64;

// Scratch (no runtime allocation allowed)
__device__ __align__(16) float g_A[ROWS * APAD];    // x@W1[0:24]+b1
__device__ __align__(16) float g_Bv[ROWS * APAD];   // x@W1[24:48]

// ---------------- f32x2 helpers ----------------
__device__ __forceinline__ u64 pk(float lo, float hi) {
    u64 r; asm("mov.b64 %0, {%1, %2};" : "=l"(r) : "f"(lo), "f"(hi)); return r;
}
__device__ __forceinline__ void upk(float& lo, float& hi, u64 v) {
    asm("mov.b64 {%0, %1}, %2;" : "=f"(lo), "=f"(hi) : "l"(v));
}
__device__ __forceinline__ u64 f2fma(u64 a, u64 b, u64 c) {
    u64 d; asm("fma.rn.f32x2 %0, %1, %2, %3;" : "=l"(d) : "l"(a), "l"(b), "l"(c)); return d;
}
__device__ __forceinline__ u64 f2add(u64 a, u64 b) {
    u64 d; asm("add.rn.f32x2 %0, %1, %2;" : "=l"(d) : "l"(a), "l"(b)); return d;
}
__device__ __forceinline__ void lds_v2u64(u64& a, u64& b, const float* p) {
    unsigned sa = (unsigned)__cvta_generic_to_shared((const void*)p);
    asm("ld.shared.v2.u64 {%0, %1}, [%2];" : "=l"(a), "=l"(b) : "r"(sa));
}
__device__ __forceinline__ u64 lds_u64(const float* p) {
    unsigned sa = (unsigned)__cvta_generic_to_shared((const void*)p);
    u64 a; asm("ld.shared.u64 %0, [%1];" : "=l"(a) : "r"(sa));
    return a;
}

// ---------------------------------------------------------------------------
// Kernel 1: precompute, 4 threads per row
// ---------------------------------------------------------------------------
__global__ void precompute_kernel(const float* __restrict__ x,
                                  const float* __restrict__ W1,
                                  const float* __restrict__ b1) {
    int t = blockIdx.x * blockDim.x + threadIdx.x;
    if (t >= ROWS * 4) return;
    int row  = t >> 2;
    int sub  = t & 3;
    int half = sub >> 1;
    int rb   = (sub & 1) * 5;

    float xv[DM];
    {
        const float4* x4 = (const float4*)(x + (size_t)row * DM);
#pragma unroll
        for (int k = 0; k < 6; k++) {
            float4 v = x4[k];
            xv[4*k] = v.x; xv[4*k+1] = v.y; xv[4*k+2] = v.z; xv[4*k+3] = v.w;
        }
    }
    const float* Wb = W1 + half * DM * RD;
    float acc[5];
#pragma unroll
    for (int r = 0; r < 5; r++) acc[r] = half ? 0.f : b1[rb + r];
#pragma unroll
    for (int d = 0; d < DM; d++) {
        float xd = xv[d];
#pragma unroll
        for (int r = 0; r < 5; r++)
            acc[r] = fmaf(xd, Wb[d * RD + rb + r], acc[r]);
    }
    float* dst = half ? g_Bv : g_A;
#pragma unroll
    for (int r = 0; r < 5; r++) dst[row * APAD + rb + r] = acc[r];
    if (rb == 5) { dst[row * APAD + 10] = 0.f; dst[row * APAD + 11] = 0.f; }
}

// ---------------------------------------------------------------------------
// Kernel 2: pairwise, TWO i's per warp. Each lane reads j-rows (lane, lane+32)
// once per 64-row chunk; those registers feed pairs for BOTH i's (4 sets:
// s = 2*iw + x). Halves lane-distinct smem traffic per pair.
// ---------------------------------------------------------------------------
__global__ __launch_bounds__(128, 4)
void pair_kernel(const float* __restrict__ q,
                 const float* __restrict__ coord,
                 const float* __restrict__ W1,
                 const float* __restrict__ W2,
                 const float* __restrict__ b2,
                 float* __restrict__ out) {
    __shared__ __align__(16) float s_cq[JCH][CQS];  // j coord/q (208B stride)
    __shared__ __align__(16) float s_bj[JCH][14];   // B_j rows (56B stride)
    __shared__ __align__(16) float s_w1[26][12];    // [d][r]; 24=qov, 25=dist
    __shared__ __align__(16) float s_w2[10][12];    // [rh][c]
    __shared__ __align__(16) float s_b2[12];
    __shared__ __align__(16) float s_ciq[8][CQS];   // per-i: -ci (0..23), qi (24..47)
    __shared__ __align__(16) float s_ai[8][12];     // per-i: A_i

    const int tid = threadIdx.x;
    const int w = tid >> 5, lane = tid & 31;
    const int i0 = blockIdx.x * 8 + 2 * w;          // warp owns i0, i0+1
    const int jbase = i0 & ~(NSEQ - 1);             // both i's in same batch (8|512)

    // --- one-time fills ---
    for (int idx = tid; idx < 26 * 12; idx += 128) {
        int d = idx / 12, r = idx % 12;
        float v = 0.f;
        if (r < RD) {
            int row = (d < 24) ? (48 + d) : (d == 24 ? 72 : 73);
            v = W1[row * RD + r];
        }
        s_w1[d][r] = v;
    }
    for (int idx = tid; idx < 10 * 12; idx += 128) {
        int rh = idx / 12, c = idx % 12;
        s_w2[rh][c] = (c < RD) ? W2[rh * RD + c] : 0.f;
    }
    if (tid < 12) s_b2[tid] = (tid < RD) ? b2[tid] : 0.f;
    if (lane < DM) {
        s_ciq[2*w][lane]        = -coord[(size_t)i0 * DM + lane];
        s_ciq[2*w][24 + lane]   = q[(size_t)i0 * DM + lane];
        s_ciq[2*w+1][lane]      = -coord[(size_t)(i0+1) * DM + lane];
        s_ciq[2*w+1][24 + lane] = q[(size_t)(i0+1) * DM + lane];
    }
    if (lane < 12) {
        s_ai[2*w][lane]   = g_A[i0 * APAD + lane];
        s_ai[2*w+1][lane] = g_A[(i0+1) * APAD + lane];
    }

    float sacc[2][RD], macc[2][RD];
#pragma unroll
    for (int iw = 0; iw < 2; iw++)
#pragma unroll
        for (int c = 0; c < RD; c++) { sacc[iw][c] = 0.f; macc[iw][c] = 0.f; }

    for (int it = 0; it < NSEQ / JCH; ++it) {
        const int jb = jbase + it * JCH;
        __syncthreads();
        // --- stage 64 j-rows (coalesced) ---
        {
            const float4* gc = (const float4*)(coord + (size_t)jb * DM);
            const float4* gq = (const float4*)(q + (size_t)jb * DM);
#pragma unroll
            for (int k = tid; k < JCH * 6; k += 128) {      // 384: 3 iters
                int r = k / 6, c = (k % 6) * 4;
                *(float4*)&s_cq[r][c]      = gc[k];
                *(float4*)&s_cq[r][24 + c] = gq[k];
            }
            const float2* gb = (const float2*)(g_Bv + (size_t)jb * APAD);
#pragma unroll
            for (int k = tid; k < JCH * 6; k += 128) {      // 384: 3 iters
                int r = k / 6, c = (k % 6) * 2;
                *(float2*)&s_bj[r][c] = gb[k];
            }
        }
        __syncthreads();

        // --- 4 sets: s = 2*iw + x, pair (i0+iw, jb + 32x + lane) ---
        u64 h2[4][5];
        u64 d2p[4], qdp[4];
#pragma unroll
        for (int iw = 0; iw < 2; iw++) {
            u64 ai[5];
#pragma unroll
            for (int t = 0; t < 5; t++) ai[t] = lds_u64(&s_ai[2*w + iw][2 * t]);
#pragma unroll
            for (int x = 0; x < 2; x++) {
                const int s = 2 * iw + x;
                d2p[s] = 0ull; qdp[s] = 0ull;
#pragma unroll
                for (int t = 0; t < 5; t++)
                    h2[s][t] = f2add(ai[t], lds_u64(&s_bj[32 * x + lane][2 * t]));
            }
        }

#pragma unroll
        for (int kk = 0; kk < 6; ++kk) {
            float4 nci[2], qi4[2];
#pragma unroll
            for (int iw = 0; iw < 2; iw++) {
                nci[iw] = *(const float4*)&s_ciq[2*w + iw][4 * kk];
                qi4[iw] = *(const float4*)&s_ciq[2*w + iw][24 + 4 * kk];
            }
            float4 cj[2], qj[2];
#pragma unroll
            for (int x = 0; x < 2; x++) {
                cj[x] = *(const float4*)&s_cq[32 * x + lane][4 * kk];
                qj[x] = *(const float4*)&s_cq[32 * x + lane][24 + 4 * kk];
            }
#pragma unroll
            for (int ep = 0; ep < 2; ep++) {
                const int d = 4 * kk + 2 * ep;
                u64 av0[4], av1[4];
#pragma unroll
                for (int iw = 0; iw < 2; iw++) {
                    u64 ncip = ep ? pk(nci[iw].z, nci[iw].w) : pk(nci[iw].x, nci[iw].y);
                    u64 qip  = ep ? pk(qi4[iw].z, qi4[iw].w) : pk(qi4[iw].x, qi4[iw].y);
#pragma unroll
                    for (int x = 0; x < 2; x++) {
                        const int s = 2 * iw + x;
                        u64 cjp = ep ? pk(cj[x].z, cj[x].w) : pk(cj[x].x, cj[x].y);
                        u64 qjp = ep ? pk(qj[x].z, qj[x].w) : pk(qj[x].x, qj[x].y);
                        u64 mdfp = f2add(ncip, cjp);          // {-df_d, -df_d+1}
                        d2p[s] = f2fma(mdfp, mdfp, d2p[s]);
                        qdp[s] = f2fma(qip, qjp, qdp[s]);
                        float m0, m1;
                        upk(m0, m1, mdfp);
                        float a0 = fabsf(m0), a1 = fabsf(m1);
                        av0[s] = pk(a0, a0);
                        av1[s] = pk(a1, a1);
                    }
                }
                u64 wA0, wA1, wA2, wA3, wA4;
                lds_v2u64(wA0, wA1, &s_w1[d][0]);
                lds_v2u64(wA2, wA3, &s_w1[d][4]);
                wA4 = lds_u64(&s_w1[d][8]);
                u64 wB0, wB1, wB2, wB3, wB4;
                lds_v2u64(wB0, wB1, &s_w1[d + 1][0]);
                lds_v2u64(wB2, wB3, &s_w1[d + 1][4]);
                wB4 = lds_u64(&s_w1[d + 1][8]);
#pragma unroll
                for (int s = 0; s < 4; s++) {
                    h2[s][0] = f2fma(av0[s], wA0, h2[s][0]);
                    h2[s][1] = f2fma(av0[s], wA1, h2[s][1]);
                    h2[s][2] = f2fma(av0[s], wA2, h2[s][2]);
                    h2[s][3] = f2fma(av0[s], wA3, h2[s][3]);
                    h2[s][4] = f2fma(av0[s], wA4, h2[s][4]);
                    h2[s][0] = f2fma(av1[s], wB0, h2[s][0]);
                    h2[s][1] = f2fma(av1[s], wB1, h2[s][1]);
                    h2[s][2] = f2fma(av1[s], wB2, h2[s][2]);
                    h2[s][3] = f2fma(av1[s], wB3, h2[s][3]);
                    h2[s][4] = f2fma(av1[s], wB4, h2[s][4]);
                }
            }
        }
        // tail features
        u64 qp[4], dp[4];
#pragma unroll
        for (int s = 0; s < 4; s++) {
            float de, do_, qe, qo;
            upk(de, do_, d2p[s]);
            upk(qe, qo, qdp[s]);
            float ds = sqrtf(de + do_);
            float qd = qe + qo;
            qp[s] = pk(qd, qd);
            dp[s] = pk(ds, ds);
        }
        {
            u64 wq0, wq1, wq2, wq3, wq4, wd0, wd1, wd2, wd3, wd4;
            lds_v2u64(wq0, wq1, &s_w1[24][0]);
            lds_v2u64(wq2, wq3, &s_w1[24][4]);
            wq4 = lds_u64(&s_w1[24][8]);
            lds_v2u64(wd0, wd1, &s_w1[25][0]);
            lds_v2u64(wd2, wd3, &s_w1[25][4]);
            wd4 = lds_u64(&s_w1[25][8]);
#pragma unroll
            for (int s = 0; s < 4; s++) {
                h2[s][0] = f2fma(qp[s], wq0, h2[s][0]); h2[s][0] = f2fma(dp[s], wd0, h2[s][0]);
                h2[s][1] = f2fma(qp[s], wq1, h2[s][1]); h2[s][1] = f2fma(dp[s], wd1, h2[s][1]);
                h2[s][2] = f2fma(qp[s], wq2, h2[s][2]); h2[s][2] = f2fma(dp[s], wd2, h2[s][2]);
                h2[s][3] = f2fma(qp[s], wq3, h2[s][3]); h2[s][3] = f2fma(dp[s], wd3, h2[s][3]);
                h2[s][4] = f2fma(qp[s], wq4, h2[s][4]); h2[s][4] = f2fma(dp[s], wd4, h2[s][4]);
            }
        }
        // relu -> hidden scalars
        float ha[4][RD];
#pragma unroll
        for (int s = 0; s < 4; s++) {
#pragma unroll
            for (int t = 0; t < 5; t++) {
                float lo, hi;
                upk(lo, hi, h2[s][t]);
                ha[s][2 * t]     = fmaxf(lo, 0.f);
                ha[s][2 * t + 1] = fmaxf(hi, 0.f);
            }
        }
        // layer 2: rh-outer, weights shared by 4 sets
        u64 r2[4][5];
#pragma unroll
        for (int t = 0; t < 5; t++) {
            u64 bb = lds_u64(&s_b2[2 * t]);
#pragma unroll
            for (int s = 0; s < 4; s++) r2[s][t] = bb;
        }
#pragma unroll
        for (int rh = 0; rh < RD; rh++) {
            u64 hh[4];
#pragma unroll
            for (int s = 0; s < 4; s++) hh[s] = pk(ha[s][rh], ha[s][rh]);
            u64 w0, w1v, w2v, w3v, w4v;
            lds_v2u64(w0, w1v, &s_w2[rh][0]);
            lds_v2u64(w2v, w3v, &s_w2[rh][4]);
            w4v = lds_u64(&s_w2[rh][8]);
#pragma unroll
            for (int s = 0; s < 4; s++) {
                r2[s][0] = f2fma(hh[s], w0,  r2[s][0]);
                r2[s][1] = f2fma(hh[s], w1v, r2[s][1]);
                r2[s][2] = f2fma(hh[s], w2v, r2[s][2]);
                r2[s][3] = f2fma(hh[s], w3v, r2[s][3]);
                r2[s][4] = f2fma(hh[s], w4v, r2[s][4]);
            }
        }
        // relu + masked accumulate (per-set target: sacc[iw])
#pragma unroll
        for (int s = 0; s < 4; s++) {
            const int iw = s >> 1, x = s & 1;
            const bool off = (jb + 32 * x + lane) != (i0 + iw);
            if (off) {
#pragma unroll
                for (int t = 0; t < 5; t++) {
                    float r0, r1;
                    upk(r0, r1, r2[s][t]);
                    r0 = fmaxf(r0, 0.f); r1 = fmaxf(r1, 0.f);
                    sacc[iw][2*t]   += r0;  macc[iw][2*t]   = fmaxf(macc[iw][2*t],   r0);
                    sacc[iw][2*t+1] += r1;  macc[iw][2*t+1] = fmaxf(macc[iw][2*t+1], r1);
                }
            }
        }
    }

    // warp reduction across j-lanes, both i's
#pragma unroll
    for (int iw = 0; iw < 2; iw++) {
#pragma unroll
        for (int c = 0; c < RD; c++) {
#pragma unroll
            for (int o = 16; o > 0; o >>= 1) {
                sacc[iw][c] += __shfl_xor_sync(0xffffffffu, sacc[iw][c], o);
                macc[iw][c] = fmaxf(macc[iw][c], __shfl_xor_sync(0xffffffffu, macc[iw][c], o));
            }
        }
    }
    if (lane == 0) {
        const float inv = 1.0f / (float)(NSEQ - 1);
#pragma unroll
        for (int iw = 0; iw < 2; iw++) {
            const int i = i0 + iw;
#pragma unroll
            for (int c = 0; c < RD; c++) {
                out[(size_t)i * RD + c] = sacc[iw][c] * inv;
                out[(size_t)ROWS * RD + (size_t)i * RD + c] = macc[iw][c];
            }
        }
    }
}

// ---------------------------------------------------------------------------
extern "C" void kernel_launch(void* const* d_in, const int* in_sizes, int n_in,
                              void* d_out, int out_size) {
    const float* x     = (const float*)d_in[0];
    const float* q     = (const float*)d_in[1];
    const float* coord = (const float*)d_in[2];
    const float* W1    = (const float*)d_in[3];
    const float* b1    = (const float*)d_in[4];
    const float* W2    = (const float*)d_in[5];
    const float* b2    = (const float*)d_in[6];
    float* out = (float*)d_out;

    precompute_kernel<<<(ROWS * 4 + 127) / 128, 128>>>(x, W1, b1);
    pair_kernel<<<ROWS / 8, 128>>>(q, coord, W1, W2, b2, out);
}